// round 8
// baseline (speedup 1.0000x reference)
#include <cuda_runtime.h>

#define N_TOTAL 10000
#define D 128
#define BSZ 100
#define FEAT 3072
#define TOPK 50
#define NTILES 79          // ceil(10000/128)
#define TRI_BLOCKS (NTILES * (NTILES + 1) / 2)
#define CAP 2048           // candidate buffer capacity in topk
#define NF4 2500           // N_TOTAL/4

// ---------------- scratch (device globals: no allocation allowed) ----------
__device__ float g_x[(size_t)N_TOTAL * D];                 // pre-BN linear out
__device__ float g_y[(size_t)N_TOTAL * D];                 // -2 * out * sw
__device__ float g_a[N_TOTAL];                             // sum_k sw*out^2
__device__ float g_scores[(size_t)N_TOTAL * N_TOTAL];      // 400 MB scratch

// ---------------- f32x2 helpers (packed FFMA2) -----------------------------
__device__ __forceinline__ float2 unpack2(unsigned long long v) {
    float x, y;
    asm("mov.b64 {%0, %1}, %2;" : "=f"(x), "=f"(y) : "l"(v));
    return make_float2(x, y);
}
__device__ __forceinline__ void fma2(unsigned long long& c,
                                     unsigned long long a,
                                     unsigned long long b) {
    asm("fma.rn.f32x2 %0, %1, %2, %3;" : "=l"(c) : "l"(a), "l"(b), "l"(c));
}

// ===========================================================================
// Kernel 1: x = inputs @ W1^T + b1      (M=10000, N=128, K=3072)
// A operand stored DUPLICATED+TRANSPOSED in shared (float2 (a,a)) so the
// mainloop is pure {4 LDS + 16 FFMA2} per kk — no pack MOVs.
// ===========================================================================
__global__ void gemm1_kernel(const float* __restrict__ A,
                             const float* __restrict__ W,
                             const float* __restrict__ b1) {
    __shared__ __align__(16) float2 As2t[32][66];   // [kk][row], (a,a) pairs
    __shared__ __align__(16) float Bs[32][132];     // [kk][col]

    const int tid = threadIdx.x;
    const int mbase = blockIdx.x * 64;
    const int r0 = (tid >> 4) * 4;
    const int c0 = (tid & 15) * 8;

    unsigned long long acc[4][4];
#pragma unroll
    for (int i = 0; i < 4; ++i)
#pragma unroll
        for (int u = 0; u < 4; ++u) acc[i][u] = 0ULL;

    const int lr = tid >> 3;          // 0..31
    const int lk = (tid & 7) * 4;     // 0,4,...,28

    for (int kc = 0; kc < FEAT; kc += 32) {
#pragma unroll
        for (int it = 0; it < 2; ++it) {
            int m = mbase + it * 32 + lr;
            float4 v = make_float4(0.f, 0.f, 0.f, 0.f);
            if (m < N_TOTAL)
                v = *(const float4*)&A[(size_t)m * FEAT + kc + lk];
            int rowi = it * 32 + lr;
            As2t[lk + 0][rowi] = make_float2(v.x, v.x);
            As2t[lk + 1][rowi] = make_float2(v.y, v.y);
            As2t[lk + 2][rowi] = make_float2(v.z, v.z);
            As2t[lk + 3][rowi] = make_float2(v.w, v.w);
        }
#pragma unroll
        for (int it = 0; it < 4; ++it) {
            int n = it * 32 + lr;     // 0..127, always valid
            float4 v = *(const float4*)&W[(size_t)n * FEAT + kc + lk];
            Bs[lk + 0][n] = v.x;
            Bs[lk + 1][n] = v.y;
            Bs[lk + 2][n] = v.z;
            Bs[lk + 3][n] = v.w;
        }
        __syncthreads();

#pragma unroll 8
        for (int kk = 0; kk < 32; ++kk) {
            ulonglong2 a01 = *(const ulonglong2*)&As2t[kk][r0];
            ulonglong2 a23 = *(const ulonglong2*)&As2t[kk][r0 + 2];
            ulonglong2 b01 = *(const ulonglong2*)&Bs[kk][c0];
            ulonglong2 b23 = *(const ulonglong2*)&Bs[kk][c0 + 4];
            fma2(acc[0][0], a01.x, b01.x); fma2(acc[0][1], a01.x, b01.y);
            fma2(acc[0][2], a01.x, b23.x); fma2(acc[0][3], a01.x, b23.y);
            fma2(acc[1][0], a01.y, b01.x); fma2(acc[1][1], a01.y, b01.y);
            fma2(acc[1][2], a01.y, b23.x); fma2(acc[1][3], a01.y, b23.y);
            fma2(acc[2][0], a23.x, b01.x); fma2(acc[2][1], a23.x, b01.y);
            fma2(acc[2][2], a23.x, b23.x); fma2(acc[2][3], a23.x, b23.y);
            fma2(acc[3][0], a23.y, b01.x); fma2(acc[3][1], a23.y, b01.y);
            fma2(acc[3][2], a23.y, b23.x); fma2(acc[3][3], a23.y, b23.y);
        }
        __syncthreads();
    }

#pragma unroll
    for (int i = 0; i < 4; ++i) {
        int m = mbase + r0 + i;
        if (m < N_TOTAL) {
#pragma unroll
            for (int u = 0; u < 4; ++u) {
                float2 c = unpack2(acc[i][u]);
                c.x += b1[c0 + 2 * u];
                c.y += b1[c0 + 2 * u + 1];
                *(float2*)&g_x[(size_t)m * D + c0 + 2 * u] = c;
            }
        }
    }
}

// ===========================================================================
// Kernel 2: BatchNorm per micro-batch of 100 rows + fused y/a computation.
// ===========================================================================
__global__ void bn_kernel(const float* __restrict__ gamma,
                          const float* __restrict__ beta,
                          const float* __restrict__ sw,
                          float* __restrict__ outp) {
    const int b = blockIdx.x;
    const int c = threadIdx.x;
    __shared__ float arow[BSZ];
    if (c < BSZ) arow[c] = 0.f;

    const float* xb = g_x + (size_t)b * BSZ * D + c;
    float s = 0.f, s2 = 0.f;
    for (int r = 0; r < BSZ; ++r) {
        float v = xb[(size_t)r * D];
        s += v;
        s2 += v * v;
    }
    float mean = s * (1.f / BSZ);
    float var = s2 * (1.f / BSZ) - mean * mean;
    float rs = rsqrtf(var + 1e-5f);
    float g = gamma[c], be = beta[c], w = sw[c];
    __syncthreads();

    const int lane = c & 31;
    for (int r = 0; r < BSZ; ++r) {
        float v = xb[(size_t)r * D];
        float o = (v - mean) * rs * g + be;
        size_t idx = (size_t)(b * BSZ + r) * D + c;
        outp[idx] = o;
        g_y[idx] = -2.f * o * w;
        float contrib = w * o * o;
#pragma unroll
        for (int off = 16; off; off >>= 1)
            contrib += __shfl_down_sync(0xffffffffu, contrib, off);
        if (lane == 0) atomicAdd(&arow[r], contrib);
    }
    __syncthreads();
    if (c < BSZ) g_a[b * BSZ + c] = arow[c];
}

// ===========================================================================
// Kernel 3: scores[i,j] = relu(a_i + a_j + sb + y_i . out_j)   (SYMMETRIC)
// Triangular launch; mirror tile written from registers.
// Mainloop per kk: 6 LDS + 32 FFMA2 (A duplicated+transposed in shared).
// ===========================================================================
__global__ void scores_kernel(const float* __restrict__ O,
                              const float* __restrict__ sbp) {
    int t = blockIdx.x;
    int bi = 0;
    while (t >= NTILES - bi) { t -= NTILES - bi; ++bi; }
    const int bj = bi + t;

    __shared__ __align__(16) float2 As2t[32][130];  // [kk][row], (a,a) pairs
    __shared__ __align__(16) float Bs[32][132];     // [kk][col]

    const int tid = threadIdx.x;
    const int ibase = bi * 128;
    const int jbase = bj * 128;
    const int r0 = (tid >> 4) * 8;
    const int c0 = (tid & 15) * 8;

    unsigned long long acc[8][4];
#pragma unroll
    for (int i = 0; i < 8; ++i)
#pragma unroll
        for (int u = 0; u < 4; ++u) acc[i][u] = 0ULL;

    const int lr = tid >> 3;
    const int lk = (tid & 7) * 4;

    for (int kc = 0; kc < D; kc += 32) {
#pragma unroll
        for (int it = 0; it < 4; ++it) {
            int m = ibase + it * 32 + lr;
            float4 v = make_float4(0.f, 0.f, 0.f, 0.f);
            if (m < N_TOTAL)
                v = *(const float4*)&g_y[(size_t)m * D + kc + lk];
            int rowi = it * 32 + lr;
            As2t[lk + 0][rowi] = make_float2(v.x, v.x);
            As2t[lk + 1][rowi] = make_float2(v.y, v.y);
            As2t[lk + 2][rowi] = make_float2(v.z, v.z);
            As2t[lk + 3][rowi] = make_float2(v.w, v.w);
        }
#pragma unroll
        for (int it = 0; it < 4; ++it) {
            int j = jbase + it * 32 + lr;
            float4 v = make_float4(0.f, 0.f, 0.f, 0.f);
            if (j < N_TOTAL)
                v = *(const float4*)&O[(size_t)j * D + kc + lk];
            Bs[lk + 0][it * 32 + lr] = v.x;
            Bs[lk + 1][it * 32 + lr] = v.y;
            Bs[lk + 2][it * 32 + lr] = v.z;
            Bs[lk + 3][it * 32 + lr] = v.w;
        }
        __syncthreads();

#pragma unroll 4
        for (int kk = 0; kk < 32; ++kk) {
            ulonglong2 a01 = *(const ulonglong2*)&As2t[kk][r0];
            ulonglong2 a23 = *(const ulonglong2*)&As2t[kk][r0 + 2];
            ulonglong2 a45 = *(const ulonglong2*)&As2t[kk][r0 + 4];
            ulonglong2 a67 = *(const ulonglong2*)&As2t[kk][r0 + 6];
            ulonglong2 b01 = *(const ulonglong2*)&Bs[kk][c0];
            ulonglong2 b23 = *(const ulonglong2*)&Bs[kk][c0 + 4];
            fma2(acc[0][0], a01.x, b01.x); fma2(acc[0][1], a01.x, b01.y);
            fma2(acc[0][2], a01.x, b23.x); fma2(acc[0][3], a01.x, b23.y);
            fma2(acc[1][0], a01.y, b01.x); fma2(acc[1][1], a01.y, b01.y);
            fma2(acc[1][2], a01.y, b23.x); fma2(acc[1][3], a01.y, b23.y);
            fma2(acc[2][0], a23.x, b01.x); fma2(acc[2][1], a23.x, b01.y);
            fma2(acc[2][2], a23.x, b23.x); fma2(acc[2][3], a23.x, b23.y);
            fma2(acc[3][0], a23.y, b01.x); fma2(acc[3][1], a23.y, b01.y);
            fma2(acc[3][2], a23.y, b23.x); fma2(acc[3][3], a23.y, b23.y);
            fma2(acc[4][0], a45.x, b01.x); fma2(acc[4][1], a45.x, b01.y);
            fma2(acc[4][2], a45.x, b23.x); fma2(acc[4][3], a45.x, b23.y);
            fma2(acc[5][0], a45.y, b01.x); fma2(acc[5][1], a45.y, b01.y);
            fma2(acc[5][2], a45.y, b23.x); fma2(acc[5][3], a45.y, b23.y);
            fma2(acc[6][0], a67.x, b01.x); fma2(acc[6][1], a67.x, b01.y);
            fma2(acc[6][2], a67.x, b23.x); fma2(acc[6][3], a67.x, b23.y);
            fma2(acc[7][0], a67.y, b01.x); fma2(acc[7][1], a67.y, b01.y);
            fma2(acc[7][2], a67.y, b23.x); fma2(acc[7][3], a67.y, b23.y);
        }
        __syncthreads();
    }

    const float sbv = *sbp;
    float ai[8], aj[8];
#pragma unroll
    for (int i = 0; i < 8; ++i) {
        int gi = ibase + r0 + i;
        ai[i] = (gi < N_TOTAL) ? g_a[gi] : 0.f;
    }
#pragma unroll
    for (int t2 = 0; t2 < 8; ++t2) {
        int gj = jbase + c0 + t2;
        aj[t2] = (gj < N_TOTAL) ? g_a[gj] : 0.f;
    }

    float sv[8][8];
#pragma unroll
    for (int i = 0; i < 8; ++i) {
        float base = ai[i] + sbv;
#pragma unroll
        for (int u = 0; u < 4; ++u) {
            float2 c = unpack2(acc[i][u]);
            sv[i][2 * u]     = fmaxf(base + aj[2 * u] + c.x, 0.f);
            sv[i][2 * u + 1] = fmaxf(base + aj[2 * u + 1] + c.y, 0.f);
        }
    }

    const bool full_i = (ibase + 128 <= N_TOTAL);
    const bool full_j = (jbase + 128 <= N_TOTAL);

    if (full_i && full_j) {
#pragma unroll
        for (int i = 0; i < 8; ++i) {
            size_t base = (size_t)(ibase + r0 + i) * N_TOTAL + jbase + c0;
            *(float4*)&g_scores[base]     = make_float4(sv[i][0], sv[i][1], sv[i][2], sv[i][3]);
            *(float4*)&g_scores[base + 4] = make_float4(sv[i][4], sv[i][5], sv[i][6], sv[i][7]);
        }
        if (bi != bj) {
#pragma unroll
            for (int j = 0; j < 8; ++j) {
                size_t base = (size_t)(jbase + c0 + j) * N_TOTAL + ibase + r0;
                *(float4*)&g_scores[base]     = make_float4(sv[0][j], sv[1][j], sv[2][j], sv[3][j]);
                *(float4*)&g_scores[base + 4] = make_float4(sv[4][j], sv[5][j], sv[6][j], sv[7][j]);
            }
        }
    } else {
#pragma unroll
        for (int i = 0; i < 8; ++i) {
            int gi = ibase + r0 + i;
            if (gi >= N_TOTAL) continue;
#pragma unroll
            for (int j = 0; j < 8; ++j) {
                int gj = jbase + c0 + j;
                if (gj >= N_TOTAL) continue;
                g_scores[(size_t)gi * N_TOTAL + gj] = sv[i][j];
                if (bi != bj)
                    g_scores[(size_t)gj * N_TOTAL + gi] = sv[i][j];
            }
        }
    }
}

// ===========================================================================
// Kernel 4: per-row exact top-50 — single-pass threshold buffer (round-6
// proven version: fused S zeroing, warp-aggregated pushes, exact radix).
// ===========================================================================
__global__ void __launch_bounds__(256) topk_kernel(float* __restrict__ S) {
    __shared__ float bval[CAP];
    __shared__ int   bidx[CAP];
    __shared__ unsigned hist[256];
    __shared__ int idxbuf[64];
    __shared__ int eqbuf[256];
    __shared__ float vbuf[TOPK];
    __shared__ float ebuf[TOPK];
    __shared__ int bcount, cnt_gt, cnt_eq;
    __shared__ unsigned sh_sel;
    __shared__ int sh_krem, sh_binc;
    __shared__ unsigned sh_thr;
    __shared__ float sh_inv;

    const int row = blockIdx.x;
    const int tid = threadIdx.x;
    const int lane = tid & 31;

    const float* rowp = g_scores + (size_t)row * N_TOTAL;
    const float4* rp4 = (const float4*)rowp;
    float4* sp4 = (float4*)(S + (size_t)row * N_TOTAL);

    if (tid == 0) { bcount = 0; cnt_gt = 0; cnt_eq = 0; sh_thr = 0; }
    __syncthreads();

#define WARP_SELECT(ARR, KREM)                                                \
    if (tid < 32) {                                                           \
        unsigned h[8], ls[8];                                                 \
        int b0 = lane * 8;                                                    \
        _Pragma("unroll")                                                     \
        for (int j = 0; j < 8; ++j) h[j] = (ARR)[b0 + j];                     \
        ls[7] = h[7];                                                         \
        _Pragma("unroll")                                                     \
        for (int j = 6; j >= 0; --j) ls[j] = ls[j + 1] + h[j];                \
        unsigned tot = ls[0];                                                 \
        unsigned ss = tot;                                                    \
        _Pragma("unroll")                                                     \
        for (int off = 1; off < 32; off <<= 1) {                              \
            unsigned o = __shfl_down_sync(0xffffffffu, ss, off);              \
            if (lane + off < 32) ss += o;                                     \
        }                                                                     \
        unsigned above = ss - tot;                                            \
        int best = -1;                                                        \
        _Pragma("unroll")                                                     \
        for (int j = 7; j >= 0; --j)                                          \
            if (best < 0 && above + ls[j] >= (unsigned)(KREM)) best = j;      \
        unsigned m = __ballot_sync(0xffffffffu, best >= 0);                   \
        int hi = 31 - __clz((int)m);                                          \
        if (lane == hi) {                                                     \
            unsigned Sb = above + ls[best];                                   \
            sh_sel = (unsigned)(b0 + best);                                   \
            sh_binc = (int)h[best];                                           \
            sh_krem = (KREM) - (int)(Sb - h[best]);                           \
        }                                                                     \
    }

#define EXACT_SELECT(CNT, KINIT, PREFIX, KREM)                                \
    {                                                                         \
        (PREFIX) = 0; (KREM) = (KINIT);                                       \
        const int SHS[4] = {24, 16, 8, 0};                                    \
        const unsigned HMS[4] = {0u, 0xFF000000u, 0xFFFF0000u, 0xFFFFFF00u};  \
        for (int ps = 0; ps < 4; ++ps) {                                      \
            hist[tid] = 0;                                                    \
            __syncthreads();                                                  \
            for (int i = tid; i < (CNT); i += 256) {                          \
                unsigned b = __float_as_uint(bval[i]);                        \
                if ((b & HMS[ps]) == ((PREFIX) & HMS[ps]))                    \
                    atomicAdd(&hist[(b >> SHS[ps]) & 255u], 1u);              \
            }                                                                 \
            __syncthreads();                                                  \
            WARP_SELECT(hist, (KREM))                                         \
            __syncthreads();                                                  \
            (PREFIX) |= sh_sel << SHS[ps];                                    \
            (KREM) = sh_krem;                                                 \
            __syncthreads();                                                  \
        }                                                                     \
    }

#define PUSH(V, IDX)                                                          \
    {                                                                         \
        unsigned b_ = __float_as_uint(V);                                     \
        if (b_ >= thr) {                                                      \
            unsigned mk = __activemask();                                     \
            int ldr = __ffs(mk) - 1;                                          \
            int rk = __popc(mk & ((1u << lane) - 1));                         \
            int bs;                                                           \
            if (lane == ldr) bs = atomicAdd(&bcount, __popc(mk));             \
            bs = __shfl_sync(mk, bs, ldr);                                    \
            int p_ = bs + rk;                                                 \
            if (p_ < CAP) { bval[p_] = (V); bidx[p_] = (IDX); }               \
        }                                                                     \
    }

    unsigned thr = 0;
    const float4 z = make_float4(0.f, 0.f, 0.f, 0.f);

    for (int chunk = 0; chunk < 10; ++chunk) {
        if (bcount > CAP - 1024) {
            unsigned pfx; int kr;
            EXACT_SELECT(bcount, TOPK, pfx, kr)
            (void)kr;
            const int cnt = bcount;
            float mv[8]; int mi[8]; int mc = 0;
            for (int i = tid; i < cnt; i += 256) {
                unsigned b = __float_as_uint(bval[i]);
                if (b >= pfx) { mv[mc] = bval[i]; mi[mc] = bidx[i]; ++mc; }
            }
            __syncthreads();
            if (tid == 0) { bcount = 0; sh_thr = pfx; }
            __syncthreads();
            for (int j = 0; j < mc; ++j) {
                int p = atomicAdd(&bcount, 1);
                bval[p] = mv[j]; bidx[p] = mi[j];
            }
            __syncthreads();
            thr = sh_thr;
        }

        int i4 = chunk * 256 + tid;
        if (i4 < NF4) {
            float4 val = rp4[i4];
            sp4[i4] = z;
            PUSH(val.x, 4 * i4 + 0)
            PUSH(val.y, 4 * i4 + 1)
            PUSH(val.z, 4 * i4 + 2)
            PUSH(val.w, 4 * i4 + 3)
        }
        __syncthreads();
    }

    const int nc = bcount;
    unsigned prefix; int krem;
    EXACT_SELECT(nc, TOPK, prefix, krem)

    for (int i = tid; i < nc; i += 256) {
        unsigned b = __float_as_uint(bval[i]);
        if (b > prefix) {
            int p = atomicAdd(&cnt_gt, 1);
            idxbuf[p] = bidx[i];
        } else if (b == prefix) {
            int p = atomicAdd(&cnt_eq, 1);
            if (p < 256) eqbuf[p] = bidx[i];
        }
    }
    __syncthreads();

    if (tid == 0) {
        int n = cnt_gt;
        int need = TOPK - n;
        if (cnt_eq <= 256) {
            for (int t = 0; t < need; ++t) {
                int best = 0x7fffffff, bj2 = 0;
                for (int j2 = 0; j2 < cnt_eq; ++j2) {
                    int vv = eqbuf[j2];
                    if (vv < best) { best = vv; bj2 = j2; }
                }
                idxbuf[n++] = best;
                eqbuf[bj2] = 0x7fffffff;
            }
        } else {
            for (int t = 0; t < need; ++t) {
                int best = 0x7fffffff, bj2 = -1;
                for (int i = 0; i < nc; ++i) {
                    if (__float_as_uint(bval[i]) == prefix && bidx[i] < best) {
                        best = bidx[i]; bj2 = i;
                    }
                }
                idxbuf[n++] = best;
                if (bj2 >= 0) bidx[bj2] = 0x7fffffff;
            }
        }
    }
    __syncthreads();

    if (tid < TOPK) vbuf[tid] = rowp[idxbuf[tid]];
    __syncthreads();
    if (tid == 0) {
        float mx = -1e30f;
        for (int t = 0; t < TOPK; ++t) mx = fmaxf(mx, vbuf[t]);
        float ssum = 0.f;
        for (int t = 0; t < TOPK; ++t) {
            float e = expf(vbuf[t] - mx);
            ebuf[t] = e;
            ssum += e;
        }
        sh_inv = 1.f / ssum;
    }
    __syncthreads();
    if (tid < TOPK)
        S[(size_t)row * N_TOTAL + idxbuf[tid]] = ebuf[tid] * sh_inv;

#undef PUSH
#undef EXACT_SELECT
#undef WARP_SELECT
}

// ===========================================================================
extern "C" void kernel_launch(void* const* d_in, const int* in_sizes, int n_in,
                              void* d_out, int out_size) {
    const float* inputs = (const float*)d_in[0];
    const float* W1     = (const float*)d_in[1];
    const float* b1     = (const float*)d_in[2];
    const float* gamma  = (const float*)d_in[3];
    const float* beta   = (const float*)d_in[4];
    const float* sw     = (const float*)d_in[5];
    const float* sb     = (const float*)d_in[6];

    float* outp = (float*)d_out;                       // [10000,128] outputs
    float* Sp   = outp + (size_t)N_TOTAL * D;          // [10000,10000] S

    gemm1_kernel<<<(N_TOTAL + 63) / 64, 256>>>(inputs, W1, b1);
    bn_kernel<<<N_TOTAL / BSZ, D>>>(gamma, beta, sw, outp);
    scores_kernel<<<TRI_BLOCKS, 256>>>(outp, sb);
    topk_kernel<<<N_TOTAL, 256>>>(Sp);
}

// round 9
// speedup vs baseline: 1.4195x; 1.4195x over previous
#include <cuda_runtime.h>

#define N_TOTAL 10000
#define D 128
#define BSZ 100
#define FEAT 3072
#define TOPK 50
#define NTILES 79          // ceil(10000/128)
#define TRI_BLOCKS (NTILES * (NTILES + 1) / 2)
#define CAP 2048           // candidate buffer capacity in topk
#define NF4 2500           // N_TOTAL/4

// ---------------- scratch (device globals: no allocation allowed) ----------
__device__ float g_x[(size_t)N_TOTAL * D];                 // pre-BN linear out
__device__ float g_y[(size_t)N_TOTAL * D];                 // -2 * out * sw
__device__ float g_a[N_TOTAL];                             // sum_k sw*out^2
__device__ float g_scores[(size_t)N_TOTAL * N_TOTAL];      // 400 MB scratch

// ---------------- f32x2 helpers (packed FFMA2) -----------------------------
__device__ __forceinline__ unsigned long long pack2(float x, float y) {
    unsigned long long r;
    asm("mov.b64 %0, {%1, %2};" : "=l"(r) : "f"(x), "f"(y));
    return r;
}
__device__ __forceinline__ float2 unpack2(unsigned long long v) {
    float x, y;
    asm("mov.b64 {%0, %1}, %2;" : "=f"(x), "=f"(y) : "l"(v));
    return make_float2(x, y);
}
__device__ __forceinline__ void fma2(unsigned long long& c,
                                     unsigned long long a,
                                     unsigned long long b) {
    asm("fma.rn.f32x2 %0, %1, %2, %3;" : "=l"(c) : "l"(a), "l"(b), "l"(c));
}

// ===========================================================================
// Kernel 1: x = inputs @ W1^T + b1      (M=10000, N=128, K=3072)
// 32-row tiles x 128 threads (313 CTAs: balanced). Columns 2t+32u ->
// bank-conflict-free LDS.64 B fetches.
// ===========================================================================
__global__ void gemm1_kernel(const float* __restrict__ A,
                             const float* __restrict__ W,
                             const float* __restrict__ b1) {
    __shared__ __align__(16) float As[32][36];
    __shared__ __align__(16) float Bs[32][132];

    const int tid = threadIdx.x;                 // 0..127
    const int mbase = blockIdx.x * 32;
    const int t = tid & 15;                      // column group
    const int r0 = (tid >> 4) * 4;               // 0,4,...,28

    unsigned long long acc[4][4];
#pragma unroll
    for (int i = 0; i < 4; ++i)
#pragma unroll
        for (int u = 0; u < 4; ++u) acc[i][u] = 0ULL;

    const int lr = tid >> 3;          // 0..15
    const int lk = (tid & 7) * 4;     // 0,4,...,28

    for (int kc = 0; kc < FEAT; kc += 32) {
#pragma unroll
        for (int it = 0; it < 2; ++it) {
            int m = mbase + it * 16 + lr;
            float4 v = make_float4(0.f, 0.f, 0.f, 0.f);
            if (m < N_TOTAL)
                v = *(const float4*)&A[(size_t)m * FEAT + kc + lk];
            *(float4*)&As[it * 16 + lr][lk] = v;
        }
#pragma unroll
        for (int it = 0; it < 8; ++it) {
            int n = it * 16 + lr;     // 0..127, always valid
            float4 v = *(const float4*)&W[(size_t)n * FEAT + kc + lk];
            Bs[lk + 0][n] = v.x;
            Bs[lk + 1][n] = v.y;
            Bs[lk + 2][n] = v.z;
            Bs[lk + 3][n] = v.w;
        }
        __syncthreads();

#pragma unroll 8
        for (int kk = 0; kk < 32; ++kk) {
            unsigned long long bv[4];
#pragma unroll
            for (int u = 0; u < 4; ++u)
                bv[u] = *(const unsigned long long*)&Bs[kk][2 * t + 32 * u];
#pragma unroll
            for (int i = 0; i < 4; ++i) {
                float av = As[r0 + i][kk];
                unsigned long long ap = pack2(av, av);
#pragma unroll
                for (int u = 0; u < 4; ++u) fma2(acc[i][u], ap, bv[u]);
            }
        }
        __syncthreads();
    }

#pragma unroll
    for (int i = 0; i < 4; ++i) {
        int m = mbase + r0 + i;
        if (m < N_TOTAL) {
#pragma unroll
            for (int u = 0; u < 4; ++u) {
                int col = 2 * t + 32 * u;
                float2 c = unpack2(acc[i][u]);
                c.x += b1[col];
                c.y += b1[col + 1];
                *(float2*)&g_x[(size_t)m * D + col] = c;
            }
        }
    }
}

// ===========================================================================
// Kernel 2: BatchNorm per micro-batch of 100 rows + fused y/a computation.
// ===========================================================================
__global__ void bn_kernel(const float* __restrict__ gamma,
                          const float* __restrict__ beta,
                          const float* __restrict__ sw,
                          float* __restrict__ outp) {
    const int b = blockIdx.x;
    const int c = threadIdx.x;
    __shared__ float arow[BSZ];
    if (c < BSZ) arow[c] = 0.f;

    const float* xb = g_x + (size_t)b * BSZ * D + c;
    float s = 0.f, s2 = 0.f;
    for (int r = 0; r < BSZ; ++r) {
        float v = xb[(size_t)r * D];
        s += v;
        s2 += v * v;
    }
    float mean = s * (1.f / BSZ);
    float var = s2 * (1.f / BSZ) - mean * mean;
    float rs = rsqrtf(var + 1e-5f);
    float g = gamma[c], be = beta[c], w = sw[c];
    __syncthreads();

    const int lane = c & 31;
    for (int r = 0; r < BSZ; ++r) {
        float v = xb[(size_t)r * D];
        float o = (v - mean) * rs * g + be;
        size_t idx = (size_t)(b * BSZ + r) * D + c;
        outp[idx] = o;
        g_y[idx] = -2.f * o * w;
        float contrib = w * o * o;
#pragma unroll
        for (int off = 16; off; off >>= 1)
            contrib += __shfl_down_sync(0xffffffffu, contrib, off);
        if (lane == 0) atomicAdd(&arow[r], contrib);
    }
    __syncthreads();
    if (c < BSZ) g_a[b * BSZ + c] = arow[c];
}

// ===========================================================================
// Kernel 3: scores[i,j] = relu(a_i + a_j + sb + y_i . out_j)   (SYMMETRIC)
// Triangular launch; mirror tile from registers. Column mapping 2t+32u ->
// conflict-free LDS.64 B fetches (was 4-way conflicted).
// ===========================================================================
__global__ void scores_kernel(const float* __restrict__ O,
                              const float* __restrict__ sbp) {
    int tt = blockIdx.x;
    int bi = 0;
    while (tt >= NTILES - bi) { tt -= NTILES - bi; ++bi; }
    const int bj = bi + tt;

    __shared__ __align__(16) float As[128][36];
    __shared__ __align__(16) float Bs[32][132];

    const int tid = threadIdx.x;
    const int ibase = bi * 128;
    const int jbase = bj * 128;
    const int t = tid & 15;                      // column group
    const int r0 = (tid >> 4) * 8;

    unsigned long long acc[8][4];
#pragma unroll
    for (int i = 0; i < 8; ++i)
#pragma unroll
        for (int u = 0; u < 4; ++u) acc[i][u] = 0ULL;

    const int lr = tid >> 3;
    const int lk = (tid & 7) * 4;

    for (int kc = 0; kc < D; kc += 32) {
#pragma unroll
        for (int it = 0; it < 4; ++it) {
            int m = ibase + it * 32 + lr;
            float4 v = make_float4(0.f, 0.f, 0.f, 0.f);
            if (m < N_TOTAL)
                v = *(const float4*)&g_y[(size_t)m * D + kc + lk];
            *(float4*)&As[it * 32 + lr][lk] = v;
        }
#pragma unroll
        for (int it = 0; it < 4; ++it) {
            int j = jbase + it * 32 + lr;
            float4 v = make_float4(0.f, 0.f, 0.f, 0.f);
            if (j < N_TOTAL)
                v = *(const float4*)&O[(size_t)j * D + kc + lk];
            Bs[lk + 0][it * 32 + lr] = v.x;
            Bs[lk + 1][it * 32 + lr] = v.y;
            Bs[lk + 2][it * 32 + lr] = v.z;
            Bs[lk + 3][it * 32 + lr] = v.w;
        }
        __syncthreads();

#pragma unroll 4
        for (int kk = 0; kk < 32; ++kk) {
            unsigned long long bv[4];
#pragma unroll
            for (int u = 0; u < 4; ++u)
                bv[u] = *(const unsigned long long*)&Bs[kk][2 * t + 32 * u];
#pragma unroll
            for (int i = 0; i < 8; ++i) {
                float av = As[r0 + i][kk];
                unsigned long long ap = pack2(av, av);
#pragma unroll
                for (int u = 0; u < 4; ++u) fma2(acc[i][u], ap, bv[u]);
            }
        }
        __syncthreads();
    }

    const float sbv = *sbp;
    float ai[8], aj[8];
#pragma unroll
    for (int i = 0; i < 8; ++i) {
        int gi = ibase + r0 + i;
        ai[i] = (gi < N_TOTAL) ? g_a[gi] : 0.f;
    }
#pragma unroll
    for (int u = 0; u < 4; ++u) {
#pragma unroll
        for (int q = 0; q < 2; ++q) {
            int gj = jbase + 2 * t + 32 * u + q;
            aj[2 * u + q] = (gj < N_TOTAL) ? g_a[gj] : 0.f;
        }
    }

    // sv[i][2u+q] corresponds to global column jbase + 2t + 32u + q
    float sv[8][8];
#pragma unroll
    for (int i = 0; i < 8; ++i) {
        float base = ai[i] + sbv;
#pragma unroll
        for (int u = 0; u < 4; ++u) {
            float2 c = unpack2(acc[i][u]);
            sv[i][2 * u]     = fmaxf(base + aj[2 * u] + c.x, 0.f);
            sv[i][2 * u + 1] = fmaxf(base + aj[2 * u + 1] + c.y, 0.f);
        }
    }

    const bool full_i = (ibase + 128 <= N_TOTAL);
    const bool full_j = (jbase + 128 <= N_TOTAL);

    if (full_i && full_j) {
#pragma unroll
        for (int i = 0; i < 8; ++i) {
            size_t rbase = (size_t)(ibase + r0 + i) * N_TOTAL + jbase + 2 * t;
#pragma unroll
            for (int u = 0; u < 4; ++u)
                *(float2*)&g_scores[rbase + 32 * u] =
                    make_float2(sv[i][2 * u], sv[i][2 * u + 1]);
        }
        if (bi != bj) {
            // mirror: column jc's 8 row-values -> row jc, cols ibase+r0..r0+7
#pragma unroll
            for (int u = 0; u < 4; ++u) {
#pragma unroll
                for (int q = 0; q < 2; ++q) {
                    int jc = jbase + 2 * t + 32 * u + q;
                    size_t base = (size_t)jc * N_TOTAL + ibase + r0;
                    int v = 2 * u + q;
                    *(float4*)&g_scores[base] =
                        make_float4(sv[0][v], sv[1][v], sv[2][v], sv[3][v]);
                    *(float4*)&g_scores[base + 4] =
                        make_float4(sv[4][v], sv[5][v], sv[6][v], sv[7][v]);
                }
            }
        }
    } else {
#pragma unroll
        for (int i = 0; i < 8; ++i) {
            int gi = ibase + r0 + i;
            if (gi >= N_TOTAL) continue;
#pragma unroll
            for (int u = 0; u < 4; ++u) {
#pragma unroll
                for (int q = 0; q < 2; ++q) {
                    int gj = jbase + 2 * t + 32 * u + q;
                    if (gj >= N_TOTAL) continue;
                    g_scores[(size_t)gi * N_TOTAL + gj] = sv[i][2 * u + q];
                    if (bi != bj)
                        g_scores[(size_t)gj * N_TOTAL + gi] = sv[i][2 * u + q];
                }
            }
        }
    }
}

// ===========================================================================
// Kernel 4: per-row exact top-50 — single-pass threshold buffer (round-6
// proven version: fused S zeroing, warp-aggregated pushes, exact radix).
// ===========================================================================
__global__ void __launch_bounds__(256) topk_kernel(float* __restrict__ S) {
    __shared__ float bval[CAP];
    __shared__ int   bidx[CAP];
    __shared__ unsigned hist[256];
    __shared__ int idxbuf[64];
    __shared__ int eqbuf[256];
    __shared__ float vbuf[TOPK];
    __shared__ float ebuf[TOPK];
    __shared__ int bcount, cnt_gt, cnt_eq;
    __shared__ unsigned sh_sel;
    __shared__ int sh_krem, sh_binc;
    __shared__ unsigned sh_thr;
    __shared__ float sh_inv;

    const int row = blockIdx.x;
    const int tid = threadIdx.x;
    const int lane = tid & 31;

    const float* rowp = g_scores + (size_t)row * N_TOTAL;
    const float4* rp4 = (const float4*)rowp;
    float4* sp4 = (float4*)(S + (size_t)row * N_TOTAL);

    if (tid == 0) { bcount = 0; cnt_gt = 0; cnt_eq = 0; sh_thr = 0; }
    __syncthreads();

#define WARP_SELECT(ARR, KREM)                                                \
    if (tid < 32) {                                                           \
        unsigned h[8], ls[8];                                                 \
        int b0 = lane * 8;                                                    \
        _Pragma("unroll")                                                     \
        for (int j = 0; j < 8; ++j) h[j] = (ARR)[b0 + j];                     \
        ls[7] = h[7];                                                         \
        _Pragma("unroll")                                                     \
        for (int j = 6; j >= 0; --j) ls[j] = ls[j + 1] + h[j];                \
        unsigned tot = ls[0];                                                 \
        unsigned ss = tot;                                                    \
        _Pragma("unroll")                                                     \
        for (int off = 1; off < 32; off <<= 1) {                              \
            unsigned o = __shfl_down_sync(0xffffffffu, ss, off);              \
            if (lane + off < 32) ss += o;                                     \
        }                                                                     \
        unsigned above = ss - tot;                                            \
        int best = -1;                                                        \
        _Pragma("unroll")                                                     \
        for (int j = 7; j >= 0; --j)                                          \
            if (best < 0 && above + ls[j] >= (unsigned)(KREM)) best = j;      \
        unsigned m = __ballot_sync(0xffffffffu, best >= 0);                   \
        int hi = 31 - __clz((int)m);                                          \
        if (lane == hi) {                                                     \
            unsigned Sb = above + ls[best];                                   \
            sh_sel = (unsigned)(b0 + best);                                   \
            sh_binc = (int)h[best];                                           \
            sh_krem = (KREM) - (int)(Sb - h[best]);                           \
        }                                                                     \
    }

#define EXACT_SELECT(CNT, KINIT, PREFIX, KREM)                                \
    {                                                                         \
        (PREFIX) = 0; (KREM) = (KINIT);                                       \
        const int SHS[4] = {24, 16, 8, 0};                                    \
        const unsigned HMS[4] = {0u, 0xFF000000u, 0xFFFF0000u, 0xFFFFFF00u};  \
        for (int ps = 0; ps < 4; ++ps) {                                      \
            hist[tid] = 0;                                                    \
            __syncthreads();                                                  \
            for (int i = tid; i < (CNT); i += 256) {                          \
                unsigned b = __float_as_uint(bval[i]);                        \
                if ((b & HMS[ps]) == ((PREFIX) & HMS[ps]))                    \
                    atomicAdd(&hist[(b >> SHS[ps]) & 255u], 1u);              \
            }                                                                 \
            __syncthreads();                                                  \
            WARP_SELECT(hist, (KREM))                                         \
            __syncthreads();                                                  \
            (PREFIX) |= sh_sel << SHS[ps];                                    \
            (KREM) = sh_krem;                                                 \
            __syncthreads();                                                  \
        }                                                                     \
    }

#define PUSH(V, IDX)                                                          \
    {                                                                         \
        unsigned b_ = __float_as_uint(V);                                     \
        if (b_ >= thr) {                                                      \
            unsigned mk = __activemask();                                     \
            int ldr = __ffs(mk) - 1;                                          \
            int rk = __popc(mk & ((1u << lane) - 1));                         \
            int bs;                                                           \
            if (lane == ldr) bs = atomicAdd(&bcount, __popc(mk));             \
            bs = __shfl_sync(mk, bs, ldr);                                    \
            int p_ = bs + rk;                                                 \
            if (p_ < CAP) { bval[p_] = (V); bidx[p_] = (IDX); }               \
        }                                                                     \
    }

    unsigned thr = 0;
    const float4 z = make_float4(0.f, 0.f, 0.f, 0.f);

    for (int chunk = 0; chunk < 10; ++chunk) {
        if (bcount > CAP - 1024) {
            unsigned pfx; int kr;
            EXACT_SELECT(bcount, TOPK, pfx, kr)
            (void)kr;
            const int cnt = bcount;
            float mv[8]; int mi[8]; int mc = 0;
            for (int i = tid; i < cnt; i += 256) {
                unsigned b = __float_as_uint(bval[i]);
                if (b >= pfx) { mv[mc] = bval[i]; mi[mc] = bidx[i]; ++mc; }
            }
            __syncthreads();
            if (tid == 0) { bcount = 0; sh_thr = pfx; }
            __syncthreads();
            for (int j = 0; j < mc; ++j) {
                int p = atomicAdd(&bcount, 1);
                bval[p] = mv[j]; bidx[p] = mi[j];
            }
            __syncthreads();
            thr = sh_thr;
        }

        int i4 = chunk * 256 + tid;
        if (i4 < NF4) {
            float4 val = rp4[i4];
            sp4[i4] = z;
            PUSH(val.x, 4 * i4 + 0)
            PUSH(val.y, 4 * i4 + 1)
            PUSH(val.z, 4 * i4 + 2)
            PUSH(val.w, 4 * i4 + 3)
        }
        __syncthreads();
    }

    const int nc = bcount;
    unsigned prefix; int krem;
    EXACT_SELECT(nc, TOPK, prefix, krem)

    for (int i = tid; i < nc; i += 256) {
        unsigned b = __float_as_uint(bval[i]);
        if (b > prefix) {
            int p = atomicAdd(&cnt_gt, 1);
            idxbuf[p] = bidx[i];
        } else if (b == prefix) {
            int p = atomicAdd(&cnt_eq, 1);
            if (p < 256) eqbuf[p] = bidx[i];
        }
    }
    __syncthreads();

    if (tid == 0) {
        int n = cnt_gt;
        int need = TOPK - n;
        if (cnt_eq <= 256) {
            for (int t2 = 0; t2 < need; ++t2) {
                int best = 0x7fffffff, bj2 = 0;
                for (int j2 = 0; j2 < cnt_eq; ++j2) {
                    int vv = eqbuf[j2];
                    if (vv < best) { best = vv; bj2 = j2; }
                }
                idxbuf[n++] = best;
                eqbuf[bj2] = 0x7fffffff;
            }
        } else {
            for (int t2 = 0; t2 < need; ++t2) {
                int best = 0x7fffffff, bj2 = -1;
                for (int i = 0; i < nc; ++i) {
                    if (__float_as_uint(bval[i]) == prefix && bidx[i] < best) {
                        best = bidx[i]; bj2 = i;
                    }
                }
                idxbuf[n++] = best;
                if (bj2 >= 0) bidx[bj2] = 0x7fffffff;
            }
        }
    }
    __syncthreads();

    if (tid < TOPK) vbuf[tid] = rowp[idxbuf[tid]];
    __syncthreads();
    if (tid == 0) {
        float mx = -1e30f;
        for (int t2 = 0; t2 < TOPK; ++t2) mx = fmaxf(mx, vbuf[t2]);
        float ssum = 0.f;
        for (int t2 = 0; t2 < TOPK; ++t2) {
            float e = expf(vbuf[t2] - mx);
            ebuf[t2] = e;
            ssum += e;
        }
        sh_inv = 1.f / ssum;
    }
    __syncthreads();
    if (tid < TOPK)
        S[(size_t)row * N_TOTAL + idxbuf[tid]] = ebuf[tid] * sh_inv;

#undef PUSH
#undef EXACT_SELECT
#undef WARP_SELECT
}

// ===========================================================================
extern "C" void kernel_launch(void* const* d_in, const int* in_sizes, int n_in,
                              void* d_out, int out_size) {
    const float* inputs = (const float*)d_in[0];
    const float* W1     = (const float*)d_in[1];
    const float* b1     = (const float*)d_in[2];
    const float* gamma  = (const float*)d_in[3];
    const float* beta   = (const float*)d_in[4];
    const float* sw     = (const float*)d_in[5];
    const float* sb     = (const float*)d_in[6];

    float* outp = (float*)d_out;                       // [10000,128] outputs
    float* Sp   = outp + (size_t)N_TOTAL * D;          // [10000,10000] S

    gemm1_kernel<<<(N_TOTAL + 31) / 32, 128>>>(inputs, W1, b1);
    bn_kernel<<<N_TOTAL / BSZ, D>>>(gamma, beta, sw, outp);
    scores_kernel<<<TRI_BLOCKS, 256>>>(outp, sb);
    topk_kernel<<<N_TOTAL, 256>>>(Sp);
}